// round 13
// baseline (speedup 1.0000x reference)
#include <cuda_runtime.h>
#include <cuda_bf16.h>

// wACSFRad R13: R11 scatter/pack (at wavefront floor) + compute divergence fix:
//   4 lanes/node (as R11 — R12's 8-lane split regressed: thread-count doubling
//   beat the divergence win), but each group processes 4 CONSECUTIVE nodes
//   sequentially: warp-max waste ~ E[max8 of sum-of-4 degrees]/4 -> ~19%
//   instead of ~38%, with FEWER threads (100k), amortized prologues, and
//   contiguous bucket/output access per warp.
//  pack:    4 nodes/thread vectorized; xyzw=(x,y,z,float(type)); cursor=0
//  scatter: 2 edges/thread, batched gathers; cull r2>=64 (fc==0, ~57% of
//           edges) and s==0; bucket[recv*CAP + atomicAdd(cursor)] = (rij, s)
//  compute: plain coalesced stores; in-kernel overflow fold-in (never taken).
//
// Inputs: z i32[100000], xyz f32[100000,3], eij i32[3200000,2], eta_mu f32[118,22,2]
// Output: f32 [100000,22]

#define N_NODES_MAX 100000
#define N_TYPES 118
#define N_PARAMS 22
#define CAP 64                   // surviving degree ~Poisson(13.8), max≈40
#define OVF_CAP 3200000          // bulletproof: can hold every edge
#define NODES_PER_GROUP 4
#define PI_OVER_CUT 0.39269908169872414f
#define LOG2E 1.4426950408889634f

__device__ float4 g_xyzw[N_NODES_MAX];
__device__ int    g_cursor[N_NODES_MAX];
__device__ __align__(16) float2 g_bucket[(long long)N_NODES_MAX * CAP]; // (rij,s)
__device__ int    g_ovf_count;
__device__ int    g_ovf_recv[OVF_CAP];
__device__ float2 g_ovf_rs[OVF_CAP];

__device__ __forceinline__ float ex2f(float x) {
    float r;
    asm("ex2.approx.f32 %0, %1;" : "=f"(r) : "f"(x));
    return r;
}

__global__ void pack_nodes_kernel(const int4* __restrict__ z4,
                                  const float4* __restrict__ xyz4, int n4) {
    const int i = blockIdx.x * blockDim.x + threadIdx.x;   // group of 4 nodes
    if (i < n4) {
        const float4 a = __ldg(&xyz4[3 * i + 0]);
        const float4 b = __ldg(&xyz4[3 * i + 1]);
        const float4 c = __ldg(&xyz4[3 * i + 2]);
        const int4  zz = __ldg(&z4[i]);
        g_xyzw[4 * i + 0] = make_float4(a.x, a.y, a.z, (float)zz.x);
        g_xyzw[4 * i + 1] = make_float4(a.w, b.x, b.y, (float)zz.y);
        g_xyzw[4 * i + 2] = make_float4(b.z, b.w, c.x, (float)zz.z);
        g_xyzw[4 * i + 3] = make_float4(c.y, c.z, c.w, (float)zz.w);
        *reinterpret_cast<int4*>(&g_cursor[4 * i]) = make_int4(0, 0, 0, 0);
    }
    if (i == 0) g_ovf_count = 0;
}

__device__ __forceinline__ void scatter_tail(int recv, float4 a, float4 b) {
    const float dx = a.x - b.x, dy = a.y - b.y, dz = a.z - b.z;
    const float r2 = fmaf(dx, dx, fmaf(dy, dy, dz * dz));
    if (r2 >= 64.0f) return;                   // fc == 0: dead edge
    const float rij = sqrtf(r2);
    const float s = 0.5f * (__cosf(rij * PI_OVER_CUT) + 1.0f) * b.w;
    if (s == 0.0f) return;                     // w == 0 senders

    const int pos = atomicAdd(&g_cursor[recv], 1);
    if (pos < CAP) {
        g_bucket[(long long)recv * CAP + pos] = make_float2(rij, s);
    } else {                                   // never at these degrees
        const int o = atomicAdd(&g_ovf_count, 1);
        if (o < OVF_CAP) {
            g_ovf_recv[o] = recv;
            g_ovf_rs[o] = make_float2(rij, s);
        }
    }
}

__global__ void __launch_bounds__(256) scatter_kernel(
    const int4* __restrict__ eij2,        // 2 edges per int4
    const int2* __restrict__ eij,
    int n_pairs, int n_edges)
{
    const int i = blockIdx.x * blockDim.x + threadIdx.x;
    if (i < n_pairs) {
        const int4 v = __ldg(&eij2[i]);
        const float4 a0 = __ldg(&g_xyzw[v.x]);
        const float4 b0 = __ldg(&g_xyzw[v.y]);
        const float4 a1 = __ldg(&g_xyzw[v.z]);
        const float4 b1 = __ldg(&g_xyzw[v.w]);
        scatter_tail(v.x, a0, b0);
        scatter_tail(v.z, a1, b1);
    }
    if (i == 0 && (n_edges & 1)) {
        const int2 t = __ldg(&eij[n_edges - 1]);
        const float4 a = __ldg(&g_xyzw[t.x]);
        const float4 b = __ldg(&g_xyzw[t.y]);
        scatter_tail(t.x, a, b);
    }
}

__global__ void __launch_bounds__(256) compute_kernel(
    const float2* __restrict__ eta_mu2,
    float* __restrict__ out,
    int n_nodes)
{
    // staged table, eta prescaled: (e2 = -eta*log2e, mu). 20768 B
    __shared__ float2 tbl[N_TYPES * N_PARAMS];
    for (int i = threadIdx.x; i < N_TYPES * N_PARAMS; i += blockDim.x) {
        const float2 p = eta_mu2[i];
        tbl[i] = make_float2(-p.x * LOG2E, p.y);
    }
    __syncthreads();

    const int gid = blockIdx.x * blockDim.x + threadIdx.x;
    const int grp = gid >> 2;                  // 4-lane group
    const int r = gid & 3;
    const int node0 = grp * NODES_PER_GROUP;   // 4 consecutive nodes per group

    #pragma unroll 1
    for (int nn = 0; nn < NODES_PER_GROUP; nn++) {
        const int node = node0 + nn;
        if (node >= n_nodes) break;

        const float4 a = __ldg(&g_xyzw[node]);
        const int t = (int)a.w;
        const int deg_raw = g_cursor[node];
        const int deg = deg_raw < CAP ? deg_raw : CAP;
        const float4* __restrict__ bkt4 =
            reinterpret_cast<const float4*>(g_bucket + (long long)node * CAP);

        // lane r owns params k = r, r+4, ... (6 slots; 2 padded in lanes 2,3)
        float e2[6], mu[6];
        #pragma unroll
        for (int j = 0; j < 6; j++) {
            const int k = r + 4 * j;
            const int kk = k < N_PARAMS ? k : (N_PARAMS - 1);
            const float2 p = tbl[t * N_PARAMS + kk];
            e2[j] = p.x; mu[j] = p.y;
        }
        float acc[6] = {0.f, 0.f, 0.f, 0.f, 0.f, 0.f};

        const int npair = deg >> 1;
        #pragma unroll 2
        for (int p = 0; p < npair; p++) {
            const float4 v = __ldg(&bkt4[p]);      // (r1, s1, r2, s2)
            #pragma unroll
            for (int q = 0; q < 6; q++) {
                const float d1 = v.x - mu[q];
                const float d2 = v.z - mu[q];
                acc[q] = fmaf(v.y, ex2f((e2[q] * d1) * d1), acc[q]);
                acc[q] = fmaf(v.w, ex2f((e2[q] * d2) * d2), acc[q]);
            }
        }
        if (deg & 1) {
            const float2 rs =
                __ldg(&reinterpret_cast<const float2*>(bkt4)[deg - 1]);
            #pragma unroll
            for (int q = 0; q < 6; q++) {
                const float d = rs.x - mu[q];
                acc[q] = fmaf(rs.y, ex2f((e2[q] * d) * d), acc[q]);
            }
        }

        // CAP-overflow fold-in (never taken at these degrees; node-local)
        if (deg_raw > CAP) {
            int count = g_ovf_count;
            if (count > OVF_CAP) count = OVF_CAP;
            for (int i = 0; i < count; i++) {
                if (g_ovf_recv[i] == node) {
                    const float2 rs = g_ovf_rs[i];
                    #pragma unroll
                    for (int q = 0; q < 6; q++) {
                        const float d = rs.x - mu[q];
                        acc[q] = fmaf(rs.y, ex2f((e2[q] * d) * d), acc[q]);
                    }
                }
            }
        }

        float* o = out + (long long)node * N_PARAMS;
        #pragma unroll
        for (int j = 0; j < 6; j++) {
            const int k = r + 4 * j;
            if (k < N_PARAMS) o[k] = acc[j];       // plain coalesced store
        }
    }
}

extern "C" void kernel_launch(void* const* d_in, const int* in_sizes, int n_in,
                              void* d_out, int out_size) {
    const int4*   z4      = (const int4*)  d_in[0];
    const float4* xyz4    = (const float4*)d_in[1];
    const int2*   eij     = (const int2*)  d_in[2];
    const int4*   eij2    = (const int4*)  d_in[2];
    const float2* eta_mu2 = (const float2*)d_in[3];
    float*        out     = (float*)d_out;

    const int n_nodes = in_sizes[0];        // 100000, divisible by 4
    const int n4 = n_nodes / 4;
    const int n_edges = in_sizes[2] / 2;
    const int n_pairs = n_edges / 2;

    pack_nodes_kernel<<<(n4 + 255) / 256, 256>>>(z4, xyz4, n4);
    scatter_kernel<<<(n_pairs + 255) / 256, 256>>>(eij2, eij, n_pairs, n_edges);

    // 4 lanes/node, 4 nodes per group -> 1 thread per node
    const int ngroups = (n_nodes + NODES_PER_GROUP - 1) / NODES_PER_GROUP;
    const int threads_needed = ngroups * 4;
    compute_kernel<<<(threads_needed + 255) / 256, 256>>>(eta_mu2, out, n_nodes);
}

// round 14
// speedup vs baseline: 1.1361x; 1.1361x over previous
#include <cuda_runtime.h>
#include <cuda_bf16.h>

// wACSFRad R14: R11 (best: 64.0us) + Programmatic Dependent Launch.
//   R12 (8 lanes/node) and R13 (4 nodes/group) both regressed -> compute keeps
//   R11's 400k-thread shape (parallelism-bound, not divergence-bound).
//   New: scatter & compute are launched with programmatic stream serialization;
//   they run their independent prologues (eij load / table staging) DURING the
//   predecessor kernel, then griddepcontrol.wait before dependent reads.
//  pack:    4 nodes/thread vectorized; xyzw=(x,y,z,float(type)); cursor=0
//  scatter: 2 edges/thread, batched gathers; cull r2>=64 (fc==0, ~57% of
//           edges) and s==0; bucket[recv*CAP + atomicAdd(cursor)] = (rij, s)
//  compute: 4 lanes/node; float4 bucket reads; ex2.approx; plain stores;
//           in-kernel overflow fold-in (never taken, correctness guard).
//
// Inputs: z i32[100000], xyz f32[100000,3], eij i32[3200000,2], eta_mu f32[118,22,2]
// Output: f32 [100000,22]

#define N_NODES_MAX 100000
#define N_TYPES 118
#define N_PARAMS 22
#define CAP 64                   // surviving degree ~Poisson(13.8), max≈40
#define OVF_CAP 3200000          // bulletproof: can hold every edge
#define PI_OVER_CUT 0.39269908169872414f
#define LOG2E 1.4426950408889634f

#define GDC_WAIT()   asm volatile("griddepcontrol.wait;" ::: "memory")
#define GDC_LAUNCH() asm volatile("griddepcontrol.launch_dependents;" ::: "memory")

__device__ float4 g_xyzw[N_NODES_MAX];
__device__ int    g_cursor[N_NODES_MAX];
__device__ __align__(16) float2 g_bucket[(long long)N_NODES_MAX * CAP]; // (rij,s)
__device__ int    g_ovf_count;
__device__ int    g_ovf_recv[OVF_CAP];
__device__ float2 g_ovf_rs[OVF_CAP];

__device__ __forceinline__ float ex2f(float x) {
    float r;
    asm("ex2.approx.f32 %0, %1;" : "=f"(r) : "f"(x));
    return r;
}

__global__ void pack_nodes_kernel(const int4* __restrict__ z4,
                                  const float4* __restrict__ xyz4, int n4) {
    const int i = blockIdx.x * blockDim.x + threadIdx.x;   // group of 4 nodes
    if (i < n4) {
        const float4 a = __ldg(&xyz4[3 * i + 0]);
        const float4 b = __ldg(&xyz4[3 * i + 1]);
        const float4 c = __ldg(&xyz4[3 * i + 2]);
        const int4  zz = __ldg(&z4[i]);
        g_xyzw[4 * i + 0] = make_float4(a.x, a.y, a.z, (float)zz.x);
        g_xyzw[4 * i + 1] = make_float4(a.w, b.x, b.y, (float)zz.y);
        g_xyzw[4 * i + 2] = make_float4(b.z, b.w, c.x, (float)zz.z);
        g_xyzw[4 * i + 3] = make_float4(c.y, c.z, c.w, (float)zz.w);
        *reinterpret_cast<int4*>(&g_cursor[4 * i]) = make_int4(0, 0, 0, 0);
    }
    if (i == 0) g_ovf_count = 0;
    GDC_LAUNCH();                 // let scatter's prologue run under our tail
}

__device__ __forceinline__ void scatter_tail(int recv, float4 a, float4 b) {
    const float dx = a.x - b.x, dy = a.y - b.y, dz = a.z - b.z;
    const float r2 = fmaf(dx, dx, fmaf(dy, dy, dz * dz));
    if (r2 >= 64.0f) return;                   // fc == 0: dead edge
    const float rij = sqrtf(r2);
    const float s = 0.5f * (__cosf(rij * PI_OVER_CUT) + 1.0f) * b.w;
    if (s == 0.0f) return;                     // w == 0 senders

    const int pos = atomicAdd(&g_cursor[recv], 1);
    if (pos < CAP) {
        g_bucket[(long long)recv * CAP + pos] = make_float2(rij, s);
    } else {                                   // never at these degrees
        const int o = atomicAdd(&g_ovf_count, 1);
        if (o < OVF_CAP) {
            g_ovf_recv[o] = recv;
            g_ovf_rs[o] = make_float2(rij, s);
        }
    }
}

__global__ void __launch_bounds__(256) scatter_kernel(
    const int4* __restrict__ eij2,        // 2 edges per int4
    const int2* __restrict__ eij,
    int n_pairs, int n_edges)
{
    const int i = blockIdx.x * blockDim.x + threadIdx.x;
    // Independent prologue: fetch edge indices (input buffer, no dependency
    // on pack). This DRAM access overlaps the pack kernel.
    int4 v = make_int4(0, 0, 0, 0);
    const bool active = (i < n_pairs);
    if (active) v = __ldg(&eij2[i]);

    GDC_WAIT();                   // pack's xyzw/cursor now visible

    if (active) {
        const float4 a0 = __ldg(&g_xyzw[v.x]);
        const float4 b0 = __ldg(&g_xyzw[v.y]);
        const float4 a1 = __ldg(&g_xyzw[v.z]);
        const float4 b1 = __ldg(&g_xyzw[v.w]);
        scatter_tail(v.x, a0, b0);
        scatter_tail(v.z, a1, b1);
    }
    if (i == 0 && (n_edges & 1)) {
        const int2 t = __ldg(&eij[n_edges - 1]);
        const float4 a = __ldg(&g_xyzw[t.x]);
        const float4 b = __ldg(&g_xyzw[t.y]);
        scatter_tail(t.x, a, b);
    }
    GDC_LAUNCH();                 // let compute's prologue run under our tail
}

__global__ void __launch_bounds__(256) compute_kernel(
    const float2* __restrict__ eta_mu2,
    float* __restrict__ out,
    int n_nodes)
{
    // Independent prologue: stage table (input buffer only). Overlaps scatter.
    __shared__ float2 tbl[N_TYPES * N_PARAMS];   // (e2 = -eta*log2e, mu)
    for (int i = threadIdx.x; i < N_TYPES * N_PARAMS; i += blockDim.x) {
        const float2 p = eta_mu2[i];
        tbl[i] = make_float2(-p.x * LOG2E, p.y);
    }

    GDC_WAIT();                   // scatter's cursor/bucket now visible
    __syncthreads();

    const int gid = blockIdx.x * blockDim.x + threadIdx.x;
    int node = gid >> 2;
    const int r = gid & 3;
    if (node >= n_nodes) node = n_nodes - 1;       // benign duplicate work

    const float4 a = __ldg(&g_xyzw[node]);
    const int t = (int)a.w;
    const int deg_raw = g_cursor[node];
    const int deg = deg_raw < CAP ? deg_raw : CAP;
    const float4* __restrict__ bkt4 =
        reinterpret_cast<const float4*>(g_bucket + (long long)node * CAP);

    // lane r owns params k = r, r+4, ... (6 slots; 2 padded in lanes 2,3)
    float e2[6], mu[6];
    #pragma unroll
    for (int j = 0; j < 6; j++) {
        const int k = r + 4 * j;
        const int kk = k < N_PARAMS ? k : (N_PARAMS - 1);
        const float2 p = tbl[t * N_PARAMS + kk];
        e2[j] = p.x; mu[j] = p.y;
    }
    float acc[6] = {0.f, 0.f, 0.f, 0.f, 0.f, 0.f};

    const int npair = deg >> 1;
    #pragma unroll 2
    for (int p = 0; p < npair; p++) {
        const float4 v = __ldg(&bkt4[p]);          // (r1, s1, r2, s2)
        #pragma unroll
        for (int q = 0; q < 6; q++) {
            const float d1 = v.x - mu[q];
            const float d2 = v.z - mu[q];
            acc[q] = fmaf(v.y, ex2f((e2[q] * d1) * d1), acc[q]);
            acc[q] = fmaf(v.w, ex2f((e2[q] * d2) * d2), acc[q]);
        }
    }
    if (deg & 1) {
        const float2 rs =
            __ldg(&reinterpret_cast<const float2*>(bkt4)[deg - 1]);
        #pragma unroll
        for (int q = 0; q < 6; q++) {
            const float d = rs.x - mu[q];
            acc[q] = fmaf(rs.y, ex2f((e2[q] * d) * d), acc[q]);
        }
    }

    // CAP-overflow fold-in (never taken at these degrees; node-local)
    if (deg_raw > CAP) {
        int count = g_ovf_count;
        if (count > OVF_CAP) count = OVF_CAP;
        for (int i = 0; i < count; i++) {
            if (g_ovf_recv[i] == node) {
                const float2 rs = g_ovf_rs[i];
                #pragma unroll
                for (int q = 0; q < 6; q++) {
                    const float d = rs.x - mu[q];
                    acc[q] = fmaf(rs.y, ex2f((e2[q] * d) * d), acc[q]);
                }
            }
        }
    }

    float* o = out + (long long)node * N_PARAMS;
    #pragma unroll
    for (int j = 0; j < 6; j++) {
        const int k = r + 4 * j;
        if (k < N_PARAMS) o[k] = acc[j];           // plain coalesced store
    }
}

extern "C" void kernel_launch(void* const* d_in, const int* in_sizes, int n_in,
                              void* d_out, int out_size) {
    const int4*   z4      = (const int4*)  d_in[0];
    const float4* xyz4    = (const float4*)d_in[1];
    const int2*   eij     = (const int2*)  d_in[2];
    const int4*   eij2    = (const int4*)  d_in[2];
    const float2* eta_mu2 = (const float2*)d_in[3];
    float*        out     = (float*)d_out;

    const int n_nodes = in_sizes[0];        // 100000, divisible by 4
    const int n4 = n_nodes / 4;
    const int n_edges = in_sizes[2] / 2;
    const int n_pairs = n_edges / 2;

    // pack: plain launch
    pack_nodes_kernel<<<(n4 + 255) / 256, 256>>>(z4, xyz4, n4);

    // PDL attribute shared by the two dependent launches
    cudaLaunchAttribute attr[1];
    attr[0].id = cudaLaunchAttributeProgrammaticStreamSerialization;
    attr[0].val.programmaticStreamSerializationAllowed = 1;

    {   // scatter with programmatic serialization (prologue overlaps pack)
        cudaLaunchConfig_t cfg = {};
        cfg.gridDim = dim3((n_pairs + 255) / 256);
        cfg.blockDim = dim3(256);
        cfg.stream = 0;
        cfg.attrs = attr;
        cfg.numAttrs = 1;
        cudaLaunchKernelEx(&cfg, scatter_kernel, eij2, eij, n_pairs, n_edges);
    }
    {   // compute with programmatic serialization (prologue overlaps scatter)
        const int threads_needed = n_nodes * 4;
        cudaLaunchConfig_t cfg = {};
        cfg.gridDim = dim3((threads_needed + 255) / 256);
        cfg.blockDim = dim3(256);
        cfg.stream = 0;
        cfg.attrs = attr;
        cfg.numAttrs = 1;
        cudaLaunchKernelEx(&cfg, compute_kernel, eta_mu2, out, n_nodes);
    }
}

// round 15
// speedup vs baseline: 1.1596x; 1.0207x over previous
#include <cuda_runtime.h>
#include <cuda_bf16.h>

// wACSFRad R15: R14 (PDL, 63.2us) + pack parallelism x2 + compute pre-wait
// prologue extension.
//   - pack: 2 nodes/thread (float2/int2), 50k threads -> 2x latency hiding.
//   - compute: node record + table + per-lane param regs set up BEFORE
//     griddepcontrol.wait (safe: pack provably complete when compute starts,
//     since scatter's wait happened-before its launch_dependents); only
//     cursor/bucket reads after the wait.
//   - scatter: unchanged (at wavefront floor: 2 irreducible divergent
//     gathers/edge; cull r2>=64 kills ~57% of edges).
//
// Inputs: z i32[100000], xyz f32[100000,3], eij i32[3200000,2], eta_mu f32[118,22,2]
// Output: f32 [100000,22]

#define N_NODES_MAX 100000
#define N_TYPES 118
#define N_PARAMS 22
#define CAP 64                   // surviving degree ~Poisson(13.8), max≈40
#define OVF_CAP 3200000          // bulletproof: can hold every edge
#define PI_OVER_CUT 0.39269908169872414f
#define LOG2E 1.4426950408889634f

#define GDC_WAIT()   asm volatile("griddepcontrol.wait;" ::: "memory")
#define GDC_LAUNCH() asm volatile("griddepcontrol.launch_dependents;" ::: "memory")

__device__ float4 g_xyzw[N_NODES_MAX];
__device__ int    g_cursor[N_NODES_MAX];
__device__ __align__(16) float2 g_bucket[(long long)N_NODES_MAX * CAP]; // (rij,s)
__device__ int    g_ovf_count;
__device__ int    g_ovf_recv[OVF_CAP];
__device__ float2 g_ovf_rs[OVF_CAP];

__device__ __forceinline__ float ex2f(float x) {
    float r;
    asm("ex2.approx.f32 %0, %1;" : "=f"(r) : "f"(x));
    return r;
}

// 2 nodes per thread: 3 float2 coord loads + 1 int2 type load, 2 float4 stores.
__global__ void pack_nodes_kernel(const int2* __restrict__ z2,
                                  const float2* __restrict__ xyz2, int n2) {
    const int i = blockIdx.x * blockDim.x + threadIdx.x;   // node pair
    if (i < n2) {
        const float2 p0 = __ldg(&xyz2[3 * i + 0]);   // x0 y0
        const float2 p1 = __ldg(&xyz2[3 * i + 1]);   // z0 x1
        const float2 p2 = __ldg(&xyz2[3 * i + 2]);   // y1 z1
        const int2  zz = __ldg(&z2[i]);
        g_xyzw[2 * i + 0] = make_float4(p0.x, p0.y, p1.x, (float)zz.x);
        g_xyzw[2 * i + 1] = make_float4(p1.y, p2.x, p2.y, (float)zz.y);
        *reinterpret_cast<int2*>(&g_cursor[2 * i]) = make_int2(0, 0);
    }
    if (i == 0) g_ovf_count = 0;
    GDC_LAUNCH();                 // scatter prologue runs under our tail
}

__device__ __forceinline__ void scatter_tail(int recv, float4 a, float4 b) {
    const float dx = a.x - b.x, dy = a.y - b.y, dz = a.z - b.z;
    const float r2 = fmaf(dx, dx, fmaf(dy, dy, dz * dz));
    if (r2 >= 64.0f) return;                   // fc == 0: dead edge
    const float rij = sqrtf(r2);
    const float s = 0.5f * (__cosf(rij * PI_OVER_CUT) + 1.0f) * b.w;
    if (s == 0.0f) return;                     // w == 0 senders

    const int pos = atomicAdd(&g_cursor[recv], 1);
    if (pos < CAP) {
        g_bucket[(long long)recv * CAP + pos] = make_float2(rij, s);
    } else {                                   // never at these degrees
        const int o = atomicAdd(&g_ovf_count, 1);
        if (o < OVF_CAP) {
            g_ovf_recv[o] = recv;
            g_ovf_rs[o] = make_float2(rij, s);
        }
    }
}

__global__ void __launch_bounds__(256) scatter_kernel(
    const int4* __restrict__ eij2,        // 2 edges per int4
    const int2* __restrict__ eij,
    int n_pairs, int n_edges)
{
    const int i = blockIdx.x * blockDim.x + threadIdx.x;
    // Independent prologue: edge indices (input buffer) — overlaps pack.
    int4 v = make_int4(0, 0, 0, 0);
    const bool active = (i < n_pairs);
    if (active) v = __ldg(&eij2[i]);

    GDC_WAIT();                   // pack's xyzw/cursor now visible

    if (active) {
        const float4 a0 = __ldg(&g_xyzw[v.x]);
        const float4 b0 = __ldg(&g_xyzw[v.y]);
        const float4 a1 = __ldg(&g_xyzw[v.z]);
        const float4 b1 = __ldg(&g_xyzw[v.w]);
        scatter_tail(v.x, a0, b0);
        scatter_tail(v.z, a1, b1);
    }
    if (i == 0 && (n_edges & 1)) {
        const int2 t = __ldg(&eij[n_edges - 1]);
        const float4 a = __ldg(&g_xyzw[t.x]);
        const float4 b = __ldg(&g_xyzw[t.y]);
        scatter_tail(t.x, a, b);
    }
    GDC_LAUNCH();                 // compute prologue runs under our tail
}

__global__ void __launch_bounds__(256) compute_kernel(
    const float2* __restrict__ eta_mu2,
    float* __restrict__ out,
    int n_nodes)
{
    // ---- pre-wait prologue (everything not written by scatter) ----
    // When compute starts, pack is provably complete (scatter waited on it
    // before launching us), so g_xyzw reads are safe here.
    __shared__ float2 tbl[N_TYPES * N_PARAMS];   // (e2 = -eta*log2e, mu)
    for (int i = threadIdx.x; i < N_TYPES * N_PARAMS; i += blockDim.x) {
        const float2 p = eta_mu2[i];
        tbl[i] = make_float2(-p.x * LOG2E, p.y);
    }

    const int gid = blockIdx.x * blockDim.x + threadIdx.x;
    int node = gid >> 2;
    const int r = gid & 3;
    if (node >= n_nodes) node = n_nodes - 1;       // benign duplicate work

    const float4 a = __ldg(&g_xyzw[node]);         // pack output: safe pre-wait
    const int t = (int)a.w;
    __syncthreads();                               // tbl staged

    float e2[6], mu[6];
    #pragma unroll
    for (int j = 0; j < 6; j++) {
        const int k = r + 4 * j;
        const int kk = k < N_PARAMS ? k : (N_PARAMS - 1);
        const float2 p = tbl[t * N_PARAMS + kk];
        e2[j] = p.x; mu[j] = p.y;
    }
    float acc[6] = {0.f, 0.f, 0.f, 0.f, 0.f, 0.f};

    GDC_WAIT();                   // scatter's cursor/bucket now visible

    const int deg_raw = g_cursor[node];
    const int deg = deg_raw < CAP ? deg_raw : CAP;
    const float4* __restrict__ bkt4 =
        reinterpret_cast<const float4*>(g_bucket + (long long)node * CAP);

    const int npair = deg >> 1;
    #pragma unroll 2
    for (int p = 0; p < npair; p++) {
        const float4 v = __ldg(&bkt4[p]);          // (r1, s1, r2, s2)
        #pragma unroll
        for (int q = 0; q < 6; q++) {
            const float d1 = v.x - mu[q];
            const float d2 = v.z - mu[q];
            acc[q] = fmaf(v.y, ex2f((e2[q] * d1) * d1), acc[q]);
            acc[q] = fmaf(v.w, ex2f((e2[q] * d2) * d2), acc[q]);
        }
    }
    if (deg & 1) {
        const float2 rs =
            __ldg(&reinterpret_cast<const float2*>(bkt4)[deg - 1]);
        #pragma unroll
        for (int q = 0; q < 6; q++) {
            const float d = rs.x - mu[q];
            acc[q] = fmaf(rs.y, ex2f((e2[q] * d) * d), acc[q]);
        }
    }

    // CAP-overflow fold-in (never taken at these degrees; node-local)
    if (deg_raw > CAP) {
        int count = g_ovf_count;
        if (count > OVF_CAP) count = OVF_CAP;
        for (int i = 0; i < count; i++) {
            if (g_ovf_recv[i] == node) {
                const float2 rs = g_ovf_rs[i];
                #pragma unroll
                for (int q = 0; q < 6; q++) {
                    const float d = rs.x - mu[q];
                    acc[q] = fmaf(rs.y, ex2f((e2[q] * d) * d), acc[q]);
                }
            }
        }
    }

    float* o = out + (long long)node * N_PARAMS;
    #pragma unroll
    for (int j = 0; j < 6; j++) {
        const int k = r + 4 * j;
        if (k < N_PARAMS) o[k] = acc[j];           // plain coalesced store
    }
}

extern "C" void kernel_launch(void* const* d_in, const int* in_sizes, int n_in,
                              void* d_out, int out_size) {
    const int2*   z2      = (const int2*)  d_in[0];
    const float2* xyz2    = (const float2*)d_in[1];
    const int2*   eij     = (const int2*)  d_in[2];
    const int4*   eij2    = (const int4*)  d_in[2];
    const float2* eta_mu2 = (const float2*)d_in[3];
    float*        out     = (float*)d_out;

    const int n_nodes = in_sizes[0];        // 100000, even
    const int n2 = n_nodes / 2;
    const int n_edges = in_sizes[2] / 2;
    const int n_pairs = n_edges / 2;

    // pack: plain launch
    pack_nodes_kernel<<<(n2 + 255) / 256, 256>>>(z2, xyz2, n2);

    cudaLaunchAttribute attr[1];
    attr[0].id = cudaLaunchAttributeProgrammaticStreamSerialization;
    attr[0].val.programmaticStreamSerializationAllowed = 1;

    {   // scatter: PDL (prologue overlaps pack)
        cudaLaunchConfig_t cfg = {};
        cfg.gridDim = dim3((n_pairs + 255) / 256);
        cfg.blockDim = dim3(256);
        cfg.stream = 0;
        cfg.attrs = attr;
        cfg.numAttrs = 1;
        cudaLaunchKernelEx(&cfg, scatter_kernel, eij2, eij, n_pairs, n_edges);
    }
    {   // compute: PDL (prologue overlaps scatter)
        const int threads_needed = n_nodes * 4;
        cudaLaunchConfig_t cfg = {};
        cfg.gridDim = dim3((threads_needed + 255) / 256);
        cfg.blockDim = dim3(256);
        cfg.stream = 0;
        cfg.attrs = attr;
        cfg.numAttrs = 1;
        cudaLaunchKernelEx(&cfg, compute_kernel, eta_mu2, out, n_nodes);
    }
}